// round 1
// baseline (speedup 1.0000x reference)
#include <cuda_runtime.h>
#include <cuda_bf16.h>
#include <math.h>

// ---------------- model constants ----------------
#define D_MODEL 768
#define N_LAYER 4
#define D_STATE 16
#define D_CONV 4
#define DT_RANK 48
#define D_INNER 1536
#define B_SZ 2
#define L_SEQ 1024
#define N_MELS 80
#define M_ROWS (B_SZ * L_SEQ)        // 2048
#define XDBL_COLS (DT_RANK + 2 * D_STATE)  // 80

// ---------------- scratch (device globals; no runtime alloc) ----------------
__device__ float g_x[M_ROWS * D_MODEL];        // residual stream
__device__ float g_h[M_ROWS * D_MODEL];        // rmsnorm output / gemm4 temp
__device__ float g_xz[M_ROWS * 2 * D_INNER];   // in_proj output
__device__ float g_xi[M_ROWS * D_INNER];       // conv+silu output (u)
__device__ float g_xdbl[M_ROWS * XDBL_COLS];   // x_proj output
__device__ float g_delta[M_ROWS * D_INNER];    // dt (after softplus)
__device__ float g_y[M_ROWS * D_INNER];        // scan output (gated)

// ---------------- generic tiled SGEMM ----------------
// C[M,N] = A[M,K](lda) * B[K,N](ldb), row-major, bounds-guarded.
template<int BM, int BN, int BK, int TM, int TN>
__global__ __launch_bounds__((BM/TM)*(BN/TN))
void sgemm_kernel(int M, int N, int K,
                  const float* __restrict__ A, int lda,
                  const float* __restrict__ B, int ldb,
                  float* __restrict__ C, int ldc)
{
    __shared__ float As[BK][BM];
    __shared__ float Bs[BK][BN];

    const int NTHREADS = (BM/TM)*(BN/TN);
    const int t  = threadIdx.x;
    const int tx = t % (BN/TN);
    const int ty = t / (BN/TN);

    const int row0 = blockIdx.y * BM;
    const int col0 = blockIdx.x * BN;

    float acc[TM][TN];
#pragma unroll
    for (int i = 0; i < TM; i++)
#pragma unroll
        for (int j = 0; j < TN; j++) acc[i][j] = 0.0f;

    for (int k0 = 0; k0 < K; k0 += BK) {
        // load A tile -> As[k][m]
#pragma unroll
        for (int i = t; i < BM * BK; i += NTHREADS) {
            int m = i / BK, k = i % BK;
            int gm = row0 + m, gk = k0 + k;
            As[k][m] = (gm < M && gk < K) ? A[(long)gm * lda + gk] : 0.0f;
        }
        // load B tile -> Bs[k][n]
#pragma unroll
        for (int i = t; i < BK * BN; i += NTHREADS) {
            int k = i / BN, n = i % BN;
            int gk = k0 + k, gn = col0 + n;
            Bs[k][n] = (gk < K && gn < N) ? B[(long)gk * ldb + gn] : 0.0f;
        }
        __syncthreads();

#pragma unroll
        for (int k = 0; k < BK; k++) {
            float a[TM], b[TN];
#pragma unroll
            for (int i = 0; i < TM; i++) a[i] = As[k][ty * TM + i];
#pragma unroll
            for (int j = 0; j < TN; j++) b[j] = Bs[k][tx * TN + j];
#pragma unroll
            for (int i = 0; i < TM; i++)
#pragma unroll
                for (int j = 0; j < TN; j++)
                    acc[i][j] = fmaf(a[i], b[j], acc[i][j]);
        }
        __syncthreads();
    }

#pragma unroll
    for (int i = 0; i < TM; i++) {
        int gm = row0 + ty * TM + i;
        if (gm >= M) continue;
#pragma unroll
        for (int j = 0; j < TN; j++) {
            int gn = col0 + tx * TN + j;
            if (gn < N) C[(long)gm * ldc + gn] = acc[i][j];
        }
    }
}

// ---------------- elementwise / small kernels ----------------
__global__ void embed_kernel(const int* __restrict__ ids,
                             const float* __restrict__ emb)
{
    int row = blockIdx.x;
    int id = ids[row];
    for (int c = threadIdx.x; c < D_MODEL; c += blockDim.x)
        g_x[row * D_MODEL + c] = emb[(long)id * D_MODEL + c];
}

__global__ void rmsnorm_kernel(const float* __restrict__ x,
                               const float* __restrict__ w,
                               float* __restrict__ out)
{
    __shared__ float red[256];
    int row = blockIdx.x;
    const float* xr = x + row * D_MODEL;
    float s = 0.0f;
    for (int c = threadIdx.x; c < D_MODEL; c += blockDim.x) {
        float v = xr[c];
        s += v * v;
    }
    red[threadIdx.x] = s;
    __syncthreads();
    for (int off = 128; off > 0; off >>= 1) {
        if (threadIdx.x < off) red[threadIdx.x] += red[threadIdx.x + off];
        __syncthreads();
    }
    float scale = rsqrtf(red[0] / (float)D_MODEL + 1e-5f);
    for (int c = threadIdx.x; c < D_MODEL; c += blockDim.x)
        out[row * D_MODEL + c] = xr[c] * scale * w[c];
}

__global__ void conv_silu_kernel(const float* __restrict__ cw,  // [D_INNER,4]
                                 const float* __restrict__ cb)  // [D_INNER]
{
    int i = blockIdx.x * blockDim.x + threadIdx.x;
    if (i >= M_ROWS * D_INNER) return;
    int row = i / D_INNER;          // b*L + l
    int d = i % D_INNER;
    int b = row / L_SEQ;
    int l = row % L_SEQ;
    float acc = cb[d];
#pragma unroll
    for (int k = 0; k < D_CONV; k++) {
        int ll = l + k - (D_CONV - 1);
        if (ll >= 0)
            acc = fmaf(g_xz[(long)(b * L_SEQ + ll) * (2 * D_INNER) + d],
                       cw[d * D_CONV + k], acc);
    }
    // silu
    float sg = 1.0f / (1.0f + __expf(-acc));
    g_xi[i] = acc * sg;
}

__global__ void bias_softplus_kernel(const float* __restrict__ bias)
{
    int i = blockIdx.x * blockDim.x + threadIdx.x;
    if (i >= M_ROWS * D_INNER) return;
    int d = i % D_INNER;
    float v = g_delta[i] + bias[d];
    float r = (v > 30.0f) ? v : log1pf(__expf(v));
    g_delta[i] = r;
}

__global__ void residual_add_kernel(void)
{
    int i = blockIdx.x * blockDim.x + threadIdx.x;
    if (i < M_ROWS * D_MODEL) g_x[i] += g_h[i];
}

// ---------------- selective scan ----------------
// One half-warp (16 lanes) per channel (b,d); lane = state index n.
// Reproduces reference numerics exactly:
//   s_l = sum_{t=1..l} max(dt_t*A, -20);  P_l = sum_{t<=l} dt_t*u_t*B_t[n] / (exp(s_t)+1e-12)
//   x_l = P_l * exp(s_l);  y_l = sum_n x_l*C_l[n] + u_l*D;  y *= silu(res)
__global__ __launch_bounds__(256)
void scan_kernel(const float* __restrict__ A_log,  // [D_INNER, D_STATE]
                 const float* __restrict__ Dp)     // [D_INNER]
{
    int tid = threadIdx.x;
    int warp = tid >> 5;
    int lane = tid & 31;
    int half = lane >> 4;
    int n = lane & 15;

    int ch = blockIdx.x * 16 + warp * 2 + half;    // 0 .. B_SZ*D_INNER-1
    int b = ch / D_INNER;
    int d = ch % D_INNER;

    float A_dn = -__expf(A_log[d * D_STATE + n]);
    float Dd = Dp[d];

    float s = 0.0f, P = 0.0f;
    long rowbase = (long)b * L_SEQ;

    for (int l = 0; l < L_SEQ; l++) {
        long row = rowbase + l;
        float dt = g_delta[row * D_INNER + d];
        float u  = g_xi[row * D_INNER + d];
        float Bn = g_xdbl[row * XDBL_COLS + DT_RANK + n];
        float Cn = g_xdbl[row * XDBL_COLS + DT_RANK + D_STATE + n];

        if (l > 0) s += fmaxf(dt * A_dn, -20.0f);
        float e = __expf(s);
        P += __fdividef(dt * u * Bn, e + 1e-12f);
        float x = P * e;
        float yp = x * Cn;

        // reduce over the 16 states (within half-warp)
#pragma unroll
        for (int off = 8; off >= 1; off >>= 1)
            yp += __shfl_xor_sync(0xffffffffu, yp, off, 16);

        if (n == 0) {
            float yv = yp + u * Dd;
            float r = g_xz[row * (2 * D_INNER) + D_INNER + d];
            float sr = r / (1.0f + __expf(-r));
            g_y[row * D_INNER + d] = yv * sr;
        }
    }
}

// ---------------- host side ----------------
static inline void* sym(const void* s)
{
    void* p = nullptr;
    cudaGetSymbolAddress(&p, s);
    return p;
}

extern "C" void kernel_launch(void* const* d_in, const int* in_sizes, int n_in,
                              void* d_out, int out_size)
{
    const int*   input_ids = (const int*)  d_in[0];
    const float* embedding = (const float*)d_in[1];
    const float* rms_w     = (const float*)d_in[2];
    const float* in_proj_w = (const float*)d_in[3];
    const float* conv_w    = (const float*)d_in[4];
    const float* conv_b    = (const float*)d_in[5];
    const float* x_proj_w  = (const float*)d_in[6];
    const float* dt_proj_w = (const float*)d_in[7];
    const float* dt_proj_b = (const float*)d_in[8];
    const float* A_log     = (const float*)d_in[9];
    const float* D_param   = (const float*)d_in[10];
    const float* out_proj_w= (const float*)d_in[11];
    const float* norm_f_w  = (const float*)d_in[12];
    const float* head_w    = (const float*)d_in[13];
    float* out = (float*)d_out;

    float* px     = (float*)sym(g_x);
    float* ph     = (float*)sym(g_h);
    float* pxz    = (float*)sym(g_xz);
    float* pxi    = (float*)sym(g_xi);
    float* pxdbl  = (float*)sym(g_xdbl);
    float* pdelta = (float*)sym(g_delta);
    float* py     = (float*)sym(g_y);

    // embed
    embed_kernel<<<M_ROWS, 256>>>(input_ids, embedding);

    for (int i = 0; i < N_LAYER; i++) {
        const float* rw  = rms_w     + (long)i * D_MODEL;
        const float* iw  = in_proj_w + (long)i * D_MODEL * 2 * D_INNER;
        const float* cw  = conv_w    + (long)i * D_INNER * D_CONV;
        const float* cb  = conv_b    + (long)i * D_INNER;
        const float* xpw = x_proj_w  + (long)i * D_INNER * XDBL_COLS;
        const float* dtw = dt_proj_w + (long)i * DT_RANK * D_INNER;
        const float* dtb = dt_proj_b + (long)i * D_INNER;
        const float* al  = A_log     + (long)i * D_INNER * D_STATE;
        const float* dp  = D_param   + (long)i * D_INNER;
        const float* ow  = out_proj_w+ (long)i * D_INNER * D_MODEL;

        // 1. h = rmsnorm(x)
        rmsnorm_kernel<<<M_ROWS, 256>>>(px, rw, ph);

        // 2. xz = h @ in_w  [2048 x 3072 x 768]
        {
            dim3 grid((2 * D_INNER + 127) / 128, (M_ROWS + 127) / 128);
            sgemm_kernel<128,128,8,8,8><<<grid, 256>>>(
                M_ROWS, 2 * D_INNER, D_MODEL, ph, D_MODEL, iw, 2 * D_INNER,
                pxz, 2 * D_INNER);
        }

        // 3. xi = silu(conv(xz[:, :1536]))
        conv_silu_kernel<<<(M_ROWS * D_INNER + 255) / 256, 256>>>(cw, cb);

        // 4. x_dbl = xi @ xp_w  [2048 x 80 x 1536]
        {
            dim3 grid((XDBL_COLS + 63) / 64, (M_ROWS + 63) / 64);
            sgemm_kernel<64,64,16,4,4><<<grid, 256>>>(
                M_ROWS, XDBL_COLS, D_INNER, pxi, D_INNER, xpw, XDBL_COLS,
                pxdbl, XDBL_COLS);
        }

        // 5. delta_raw = x_dbl[:, :48] @ dt_w  [2048 x 1536 x 48]
        {
            dim3 grid((D_INNER + 127) / 128, (M_ROWS + 127) / 128);
            sgemm_kernel<128,128,8,8,8><<<grid, 256>>>(
                M_ROWS, D_INNER, DT_RANK, pxdbl, XDBL_COLS, dtw, D_INNER,
                pdelta, D_INNER);
        }

        // 6. delta = softplus(delta_raw + dt_b)
        bias_softplus_kernel<<<(M_ROWS * D_INNER + 255) / 256, 256>>>(dtb);

        // 7. selective scan + gating -> g_y
        scan_kernel<<<(B_SZ * D_INNER) / 16, 256>>>(al, dp);

        // 8. h_tmp = y @ out_w  [2048 x 768 x 1536]
        {
            dim3 grid((D_MODEL + 127) / 128, (M_ROWS + 127) / 128);
            sgemm_kernel<128,128,8,8,8><<<grid, 256>>>(
                M_ROWS, D_MODEL, D_INNER, py, D_INNER, ow, D_MODEL,
                ph, D_MODEL);
        }

        // 9. x += h_tmp
        residual_add_kernel<<<(M_ROWS * D_MODEL + 255) / 256, 256>>>();
    }

    // final rmsnorm + head
    rmsnorm_kernel<<<M_ROWS, 256>>>(px, norm_f_w, ph);
    {
        dim3 grid((N_MELS + 63) / 64, (M_ROWS + 63) / 64);
        sgemm_kernel<64,64,16,4,4><<<grid, 256>>>(
            M_ROWS, N_MELS, D_MODEL, ph, D_MODEL, head_w, N_MELS,
            out, N_MELS);
    }
}